// round 17
// baseline (speedup 1.0000x reference)
#include <cuda_runtime.h>
#include <cstdint>

// LSTM B=4096 T=256 I=8 H=32 O=1.
// NB=2 high-occupancy design with hoisted input projection:
//  - CTA = 32 thr = 1 warp = 2 sequences; grid = 2048. __launch_bounds__(32,13)
//    -> reg cap 157, 13 CTAs/SM resident, 3.25 warps/SMSP (2x prior designs).
//  - lane j = hidden unit j. f32x2 lanes are GATE pairs {z_i,z_f},{z_g,z_o}.
//  - W_hh in regs as NATURAL gate pairs (128 regs).
//  - z0 = bias + W_ih x_t precomputed per 8-step chunk into smem (independent
//    of recurrence) -> hot loop = recurrent matvec + activations only.
//  - h PRE-DUPLICATED ({h,h} u64) in smem, double-buffered: k-iter =
//    1 broadcast LDS.128 + 4 FFMA2.
//  - tanh.approx; sigmoid 0.5 scale folded into i,f,o weights/biases.

#define B_TOT 4096
#define T_TOT 256
#define I_SZ 8
#define CHUNK 8
#define NCHUNK (T_TOT / CHUNK)

typedef unsigned long long u64;

__device__ __forceinline__ u64 pack2(float a, float b) {
    u64 r; asm("mov.b64 %0,{%1,%2};" : "=l"(r) : "f"(a), "f"(b)); return r;
}
__device__ __forceinline__ void unpack2(u64 v, float& a, float& b) {
    asm("mov.b64 {%0,%1},%2;" : "=f"(a), "=f"(b) : "l"(v));
}
__device__ __forceinline__ u64 fma2(u64 a, u64 b, u64 c) {
    u64 d; asm("fma.rn.f32x2 %0,%1,%2,%3;" : "=l"(d) : "l"(a), "l"(b), "l"(c)); return d;
}
__device__ __forceinline__ float tanhap(float x) {
    float y; asm("tanh.approx.f32 %0,%1;" : "=f"(y) : "f"(x)); return y;
}
// i,f,o accumulators pre-scaled by 0.5: sigmoid(z)=0.5*tanh(z/2)+0.5
__device__ __forceinline__ float sig_h(float zhalf) {
    return fmaf(0.5f, tanhap(zhalf), 0.5f);
}

__global__ void __launch_bounds__(32, 13)
lstm_kernel(const float* __restrict__ x,
            const float* __restrict__ W_ih,
            const float* __restrict__ W_hh,
            const float* __restrict__ b_ih,
            const float* __restrict__ b_hh,
            const float* __restrict__ W_out,
            const float* __restrict__ b_out,
            float* __restrict__ out)
{
    // per-CTA shared
    __shared__ __align__(16) ulonglong2 wi_sm[I_SZ * 32];   // [i][j] {wif},{wgo}
    __shared__ __align__(16) u64 z0_sm[CHUNK * 4 * 32];     // [t][p][j]; p: if0,if1,go0,go1
    __shared__ __align__(16) u64 hbuf[2 * 32 * 2];          // [cur][k][{h0,h0},{h1,h1}]

    const int lane = threadIdx.x & 31;

    // ---- W_hh rows -> registers as natural gate pairs (i,f,o x0.5) ----
    u64 wif[32], wgo[32];
    {
        const float* ri = W_hh + (0 * 32 + lane) * 32;
        const float* rf = W_hh + (1 * 32 + lane) * 32;
        const float* rg = W_hh + (2 * 32 + lane) * 32;
        const float* ro = W_hh + (3 * 32 + lane) * 32;
#pragma unroll
        for (int kk = 0; kk < 8; ++kk) {
            const float4 ai = *(const float4*)(ri + kk * 4);
            const float4 af = *(const float4*)(rf + kk * 4);
            const float4 ag = *(const float4*)(rg + kk * 4);
            const float4 ao = *(const float4*)(ro + kk * 4);
            wif[kk * 4 + 0] = pack2(0.5f * ai.x, 0.5f * af.x);
            wif[kk * 4 + 1] = pack2(0.5f * ai.y, 0.5f * af.y);
            wif[kk * 4 + 2] = pack2(0.5f * ai.z, 0.5f * af.z);
            wif[kk * 4 + 3] = pack2(0.5f * ai.w, 0.5f * af.w);
            wgo[kk * 4 + 0] = pack2(ag.x, 0.5f * ao.x);
            wgo[kk * 4 + 1] = pack2(ag.y, 0.5f * ao.y);
            wgo[kk * 4 + 2] = pack2(ag.z, 0.5f * ao.z);
            wgo[kk * 4 + 3] = pack2(ag.w, 0.5f * ao.w);
        }
    }

    // ---- W_ih gate pairs -> smem (read during staging only) ----
#pragma unroll
    for (int i = 0; i < I_SZ; ++i) {
        const float a = 0.5f * W_ih[(0 * 32 + lane) * I_SZ + i];
        const float b = 0.5f * W_ih[(1 * 32 + lane) * I_SZ + i];
        const float c =        W_ih[(2 * 32 + lane) * I_SZ + i];
        const float d = 0.5f * W_ih[(3 * 32 + lane) * I_SZ + i];
        wi_sm[i * 32 + lane] = make_ulonglong2(pack2(a, b), pack2(c, d));
    }

    // ---- zero h buffer ----
    hbuf[lane * 2 + 0] = 0ull;
    hbuf[lane * 2 + 1] = 0ull;
    hbuf[64 + lane * 2 + 0] = 0ull;
    hbuf[64 + lane * 2 + 1] = 0ull;

    // ---- biases (gate pairs, i/f/o pre-scaled) ----
    const float bi_ = 0.5f * (b_ih[0 * 32 + lane] + b_hh[0 * 32 + lane]);
    const float bf_ = 0.5f * (b_ih[1 * 32 + lane] + b_hh[1 * 32 + lane]);
    const float bg_ =         b_ih[2 * 32 + lane] + b_hh[2 * 32 + lane];
    const float bo_ = 0.5f * (b_ih[3 * 32 + lane] + b_hh[3 * 32 + lane]);
    const u64 bif = pack2(bi_, bf_);
    const u64 bgo = pack2(bg_, bo_);

    float c0 = 0.f, c1 = 0.f, h0 = 0.f, h1 = 0.f;
    int cur = 0;

    const float* xb0 = x + (size_t)(blockIdx.x * 2 + 0) * T_TOT * I_SZ;
    const float* xb1 = x + (size_t)(blockIdx.x * 2 + 1) * T_TOT * I_SZ;

    __syncwarp();

#pragma unroll 1
    for (int tc = 0; tc < NCHUNK; ++tc) {
        // ---- staging: z0[t] = bias + W_ih x_t for both batches, 8 steps ----
#pragma unroll 1
        for (int t = 0; t < CHUNK; ++t) {
            const float4 va = *(const float4*)(xb0 + (size_t)(tc * CHUNK + t) * I_SZ);
            const float4 vb = *(const float4*)(xb0 + (size_t)(tc * CHUNK + t) * I_SZ + 4);
            const float4 vc = *(const float4*)(xb1 + (size_t)(tc * CHUNK + t) * I_SZ);
            const float4 vd = *(const float4*)(xb1 + (size_t)(tc * CHUNK + t) * I_SZ + 4);

            u64 aif0 = bif, ago0 = bgo, aif1 = bif, ago1 = bgo;
            const float x0v[8] = { va.x, va.y, va.z, va.w, vb.x, vb.y, vb.z, vb.w };
            const float x1v[8] = { vc.x, vc.y, vc.z, vc.w, vd.x, vd.y, vd.z, vd.w };
#pragma unroll
            for (int i = 0; i < I_SZ; ++i) {
                const ulonglong2 wv = wi_sm[i * 32 + lane];
                const u64 xd0 = pack2(x0v[i], x0v[i]);
                const u64 xd1 = pack2(x1v[i], x1v[i]);
                aif0 = fma2(xd0, wv.x, aif0); ago0 = fma2(xd0, wv.y, ago0);
                aif1 = fma2(xd1, wv.x, aif1); ago1 = fma2(xd1, wv.y, ago1);
            }
            z0_sm[(t * 4 + 0) * 32 + lane] = aif0;
            z0_sm[(t * 4 + 1) * 32 + lane] = aif1;
            z0_sm[(t * 4 + 2) * 32 + lane] = ago0;
            z0_sm[(t * 4 + 3) * 32 + lane] = ago1;
        }
        __syncwarp();

        // ---- hot loop: recurrence only ----
#pragma unroll 1
        for (int s = 0; s < CHUNK; ++s) {
            u64 zif0 = z0_sm[(s * 4 + 0) * 32 + lane];
            u64 zif1 = z0_sm[(s * 4 + 1) * 32 + lane];
            u64 zgo0 = z0_sm[(s * 4 + 2) * 32 + lane];
            u64 zgo1 = z0_sm[(s * 4 + 3) * 32 + lane];

            const u64* hr = hbuf + cur * 64;
#pragma unroll
            for (int k = 0; k < 32; ++k) {
                const ulonglong2 hv = *(const ulonglong2*)(hr + k * 2);
                zif0 = fma2(hv.x, wif[k], zif0);
                zgo0 = fma2(hv.x, wgo[k], zgo0);
                zif1 = fma2(hv.y, wif[k], zif1);
                zgo1 = fma2(hv.y, wgo[k], zgo1);
            }

            float zi, zf, zg, zo;
            unpack2(zif0, zi, zf); unpack2(zgo0, zg, zo);
            c0 = fmaf(sig_h(zf), c0, sig_h(zi) * tanhap(zg));
            h0 = sig_h(zo) * tanhap(c0);

            unpack2(zif1, zi, zf); unpack2(zgo1, zg, zo);
            c1 = fmaf(sig_h(zf), c1, sig_h(zi) * tanhap(zg));
            h1 = sig_h(zo) * tanhap(c1);

            // publish duplicated h (conflict-free STS.128)
            *(float4*)(hbuf + (cur ^ 1) * 64 + lane * 2) = make_float4(h0, h0, h1, h1);
            cur ^= 1;
            __syncwarp();
        }
    }

    // ---- output head: out[b] = sum_j h[b][j]*W_out[j] + b_out ----
    const float wo = W_out[lane];
    float v0 = h0 * wo, v1 = h1 * wo;
#pragma unroll
    for (int off = 16; off; off >>= 1) {
        v0 += __shfl_xor_sync(0xffffffffu, v0, off);
        v1 += __shfl_xor_sync(0xffffffffu, v1, off);
    }
    if (lane == 0) {
        const float bout = b_out[0];
        out[blockIdx.x * 2 + 0] = v0 + bout;
        out[blockIdx.x * 2 + 1] = v1 + bout;
    }
}

extern "C" void kernel_launch(void* const* d_in, const int* in_sizes, int n_in,
                              void* d_out, int out_size)
{
    const float* x     = (const float*)d_in[0];
    const float* W_ih  = (const float*)d_in[1];
    const float* W_hh  = (const float*)d_in[2];
    const float* b_ih  = (const float*)d_in[3];
    const float* b_hh  = (const float*)d_in[4];
    const float* W_out = (const float*)d_in[5];
    const float* b_out = (const float*)d_in[6];
    float* out = (float*)d_out;

    lstm_kernel<<<B_TOT / 2, 32>>>(x, W_ih, W_hh, b_ih, b_hh, W_out, b_out, out);
}